// round 16
// baseline (speedup 1.0000x reference)
#include <cuda_runtime.h>

#define BATCH 1024
#define RC 64
#define NL 24
#define QL 128
#define TB 4                     // batch rows per compute block
#define NCOMP (BATCH / TB)       // 256 compute blocks
#define CTHREADS 512             // 2 independent groups of 256
#define NTHREADS 256
#define NQ ((size_t)NL * BATCH * RC * QL)   // 201326592 queue elements
#define NROWS (NQ / 128)                    // 1572864 rows of 128 floats
#define LSTR ((size_t)BATCH * RC)           // row index stride per layer
#define NCONVP (NL * 32 * 256)              // packed conv float4 count
#define NFC1P  (NL * 16 * 256)              // packed fc1 float4 count

// ---- copy kernel geometry: 4-row groups are contiguous+aligned in dst ----
#define BG 8                                // 4-row groups per copy block
#define CP_ROWS (4 * BG)                    // 32 rows per block
#define CP_SRC_F4 (CP_ROWS * 128 / 4)       // 1024 src float4 per block
#define CP_DST_F  (CP_ROWS * 129)           // 4128 dst floats per block
#define CP_DST_F4 (CP_DST_F / 4)            // 1032 dst float4 per block
#define NCOPY ((int)(NROWS / CP_ROWS))      // 49152 copy blocks

typedef unsigned long long u64;

// Packed transposed weights, lane-coalesced for thread==j mapping.
// g_convP[(i*32+p)*256+j] = (w0[2p], w0[2p+1], w1[2p], w1[2p+1])
//   -> as ulonglong2: .x = f32x2 pair of w0, .y = f32x2 pair of w1
// g_fc1P [(i*16+q)*256+j] = fc1[rc=4q..4q+3] (two natural f32x2 pairs)
__device__ float4 g_convP[NCONVP];
__device__ float4 g_fc1P[NFC1P];

// Fast MUFU-based activations (rcp.approx + ex2.approx; ~1e-6 rel err).
__device__ __forceinline__ float sigf(float x) {
    return __fdividef(1.0f, 1.0f + __expf(-x));
}
__device__ __forceinline__ float tanhf_fast(float x) {
    return 1.0f - __fdividef(2.0f, __expf(2.0f * x) + 1.0f);
}

__device__ __forceinline__ void fma2(u64& d, u64 a, u64 b) {
    asm("fma.rn.f32x2 %0, %1, %2, %3;" : "=l"(d) : "l"(a), "l"(b), "l"(d));
}
__device__ __forceinline__ u64 pk(float lo, float hi) {
    u64 r; asm("mov.b64 %0, {%1, %2};" : "=l"(r) : "f"(lo), "f"(hi)); return r;
}
__device__ __forceinline__ float hadd2(u64 v) {
    float lo, hi;
    asm("mov.b64 {%0, %1}, %2;" : "=f"(lo), "=f"(hi) : "l"(v));
    return lo + hi;
}

#define GBAR(g) asm volatile("bar.sync %0, %1;" :: "r"((g) + 1), "r"(256) : "memory")

// ---------------------------------------------------------------------------
// WEIGHT TRANSPOSE (packed float4, rc-pairwise reorder for f32x2)
// ---------------------------------------------------------------------------
__global__ void __launch_bounds__(NTHREADS)
transpose_weights_kernel(const float* __restrict__ conv_w,
                         const float* __restrict__ fc1_w)
{
    int idx = blockIdx.x * NTHREADS + threadIdx.x;   // ((i*32+p)*256+j)
    if (idx < NCONVP) {
        int j  = idx & 255;
        int pi = idx >> 8;           // i*32 + p
        int p  = pi & 31;
        int i  = pi >> 5;
        float4 v =
            __ldg((const float4*)(conv_w + (((size_t)i * 256 + j) << 7)) + p);
        // src float4 #p = (w0[2p], w1[2p], w0[2p+1], w1[2p+1])
        g_convP[idx] = make_float4(v.x, v.z, v.y, v.w);
    }
    if (idx < NFC1P) {
        int j  = idx & 255;
        int qi = idx >> 8;           // i*16 + q
        g_fc1P[idx] =
            __ldg((const float4*)(fc1_w + (size_t)j * (NL * RC)) + qi);
    }
}

// ---------------------------------------------------------------------------
// COPY KERNEL v2: fully-aligned stream copy with smem hole insertion.
// (Proven: 228us standalone, 86.5% DRAM.)
// ---------------------------------------------------------------------------
__global__ void __launch_bounds__(NTHREADS)
queue_copy_kernel(const float* __restrict__ queues, float* __restrict__ out)
{
    __shared__ __align__(16) float st[CP_DST_F];
    const int tid = threadIdx.x;
    const size_t blk = blockIdx.x;

    const float4* __restrict__ s4 = (const float4*)queues + blk * CP_SRC_F4;
    #pragma unroll
    for (int k = 0; k < CP_SRC_F4 / NTHREADS; k++) {      // 4 iterations
        int e4 = k * NTHREADS + tid;
        float4 v = __ldcs(&s4[e4]);
        int e  = e4 * 4;
        int ep = e + (e >> 7);
        st[ep]     = v.x;
        st[ep + 1] = v.y;
        st[ep + 2] = v.z;
        st[ep + 3] = v.w;
    }
    if (tid < CP_ROWS) st[tid * 129 + 128] = 0.0f;        // junk in holes
    __syncthreads();

    float4* __restrict__ d4 = (float4*)(out + BATCH) + blk * CP_DST_F4;
    #pragma unroll
    for (int k = 0; k < (CP_DST_F4 + NTHREADS - 1) / NTHREADS; k++) {
        int e4 = k * NTHREADS + tid;
        if (e4 < CP_DST_F4)
            __stcs(&d4[e4], *(const float4*)&st[e4 * 4]);
    }
}

// ---------------------------------------------------------------------------
// COMPUTE KERNEL: 512 threads, TB=4 rows, two independent 256-thread groups
// (group g owns rows {2g, 2g+1}); per-layer group-local barriers. fc1 of
// layer i-1 fused into layer i's conv loop; packed f32x2 FMAs. Gates use
// MUFU-based sigmoid/tanh. Next layer's first weight chunk is prefetched
// before the gate barriers so its L2 latency hides behind the gate phase.
// ---------------------------------------------------------------------------
__global__ void __launch_bounds__(CTHREADS, 2)
wave_compute_kernel(const float* __restrict__ x,
                    const float* __restrict__ features,
                    const float* __restrict__ queues,
                    const float* __restrict__ fc_h_w,
                    const float* __restrict__ fc_h_b,
                    const float* __restrict__ fc_c_w,
                    const float* __restrict__ fc_c_b,
                    const float* __restrict__ conv_b,
                    const float* __restrict__ fc1_b,
                    const float* __restrict__ fc2_w,
                    const float* __restrict__ fc2_b,
                    float* __restrict__ out)
{
    __shared__ __align__(16) float s_h[TB][RC];
    __shared__ __align__(16) float s_c[TB][RC];
    __shared__ __align__(16) float s_pv[NL][TB][RC];   // 24 KB prefetched slices
    __shared__ float s_co[TB][4 * RC];

    const int tid = threadIdx.x;
    const int b0  = blockIdx.x * TB;
    const int g   = tid >> 8;          // group 0/1: owns rows t0, t0+1
    const int lid = tid & 255;         // id within group
    const int j   = lid;               // output channel
    const int t0  = g * 2;

    // ---- prefetch ALL 24 layers' dilated queue values into shared ----
    for (int idx = tid; idx < NL * TB * RC; idx += CTHREADS) {
        int i = idx >> 8;              // / (TB*RC)
        int t = (idx >> 6) & 3;
        int r = idx & 63;
        s_pv[i][t][r] = __ldg(queues
            + (((size_t)(b0 + t) * RC + r) + (size_t)i * LSTR) * QL
            + QL - (1 << (i & 7)));
    }

    // ---- initial h, c (each group inits its own 2 rows; 128 threads) ----
    float* __restrict__ outq = out + BATCH;
    if (lid < 128) {
        int t = t0 + (lid >> 6), r = lid & 63;
        int b = b0 + t;
        const float* wh = fc_h_w + r * 33;
        const float* wc = fc_c_w + r * 33;
        float ah = fc_h_b[r], ac = fc_c_b[r];
        float xv = x[b];
        ah += xv * wh[0];
        ac += xv * wc[0];
        const float* fb = features + b * 32;
        #pragma unroll
        for (int k = 0; k < 32; k++) {
            float f = fb[k];
            ah += f * wh[1 + k];
            ac += f * wc[1 + k];
        }
        float h0 = tanhf_fast(ah);
        s_h[t][r] = h0;
        s_c[t][r] = tanhf_fast(ac);
        outq[((size_t)b * RC + r) * 129 + QL] = h0;    // entry for layer 0
    }

    u64 y0 = pk(fc1_b[j], 0.0f), y1 = y0;

    const ulonglong2* __restrict__ wcv = (const ulonglong2*)g_convP + j;
    const ulonglong2* __restrict__ wf1 = (const ulonglong2*)g_fc1P  + j;

    // Prefetch layer 0's chunk-0 weights; fc1 pair starts as packed zeros
    // (layer 0 has no fused fc1 -> fma with 0.0 is a no-op).
    ulonglong2 pwA = __ldg(&wcv[0]);
    ulonglong2 pwB = __ldg(&wcv[256]);
    ulonglong2 pfA = make_ulonglong2(0ull, 0ull);

    __syncthreads();                   // s_pv + init visible to all

    for (int i = 0; i < NL; i++) {
        // ---- conv layer i (+ fused fc1 of layer i-1, same s_h reads) ----
        u64 acc0 = pk(__ldg(conv_b + i * 256 + j), 0.0f);
        u64 acc1 = acc0;
        const ulonglong2* wci = wcv + (size_t)i * (32 * 256);
        const ulonglong2* f1p = wf1 + (size_t)(i - 1) * (16 * 256);

        // rc = 0..3 uses the prefetched chunk
        {
            ulonglong2 P = *(const ulonglong2*)&s_pv[i][t0][0];
            ulonglong2 H = *(const ulonglong2*)&s_h[t0][0];
            fma2(acc0, P.x, pwA.x);
            fma2(acc0, H.x, pwA.y);
            fma2(acc0, P.y, pwB.x);
            fma2(acc0, H.y, pwB.y);
            fma2(y0,   H.x, pfA.x);
            fma2(y0,   H.y, pfA.y);
            ulonglong2 Q = *(const ulonglong2*)&s_pv[i][t0 + 1][0];
            ulonglong2 G = *(const ulonglong2*)&s_h[t0 + 1][0];
            fma2(acc1, Q.x, pwA.x);
            fma2(acc1, G.x, pwA.y);
            fma2(acc1, Q.y, pwB.x);
            fma2(acc1, G.y, pwB.y);
            fma2(y1,   G.x, pfA.x);
            fma2(y1,   G.y, pfA.y);
        }

        #pragma unroll 4
        for (int rc = 4; rc < RC; rc += 4) {
            // wA: rc,rc+1  (.x = w0 pair, .y = w1 pair); wB: rc+2,rc+3
            ulonglong2 wA = __ldg(&wci[((rc >> 1)    ) << 8]);
            ulonglong2 wB = __ldg(&wci[((rc >> 1) + 1) << 8]);
            ulonglong2 fA = (i > 0) ? __ldg(&f1p[(rc >> 2) << 8])
                                    : make_ulonglong2(0ull, 0ull);
            {
                ulonglong2 P = *(const ulonglong2*)&s_pv[i][t0][rc];
                ulonglong2 H = *(const ulonglong2*)&s_h[t0][rc];
                fma2(acc0, P.x, wA.x);
                fma2(acc0, H.x, wA.y);
                fma2(acc0, P.y, wB.x);
                fma2(acc0, H.y, wB.y);
                fma2(y0,   H.x, fA.x);
                fma2(y0,   H.y, fA.y);
            }
            {
                ulonglong2 P = *(const ulonglong2*)&s_pv[i][t0 + 1][rc];
                ulonglong2 H = *(const ulonglong2*)&s_h[t0 + 1][rc];
                fma2(acc1, P.x, wA.x);
                fma2(acc1, H.x, wA.y);
                fma2(acc1, P.y, wB.x);
                fma2(acc1, H.y, wB.y);
                fma2(y1,   H.x, fA.x);
                fma2(y1,   H.y, fA.y);
            }
        }
        s_co[t0][j]     = hadd2(acc0);
        s_co[t0 + 1][j] = hadd2(acc1);

        // ---- prefetch NEXT layer's chunk-0 weights (hides L2 latency
        //      behind the barrier + gate phase) ----
        if (i + 1 < NL) {
            const ulonglong2* wcn = wcv + (size_t)(i + 1) * (32 * 256);
            pwA = __ldg(&wcn[0]);
            pwB = __ldg(&wcn[256]);
            pfA = __ldg(&wf1[(size_t)i * (16 * 256)]);   // fc1 of layer i
        }
        GBAR(g);                       // group-local: s_co rows ready

        // ---- gate update: lower 128 threads of this group, own rows ----
        if (lid < 128) {
            int t = t0 + (lid >> 6), r = lid & 63;
            float ig = s_co[t][r];
            float cf = s_co[t][RC + r];
            float cg = s_co[t][2 * RC + r];
            float eg = s_co[t][3 * RC + r];
            float c = sigf(ig) * s_c[t][r] + tanhf_fast(cf) * sigf(cg);
            float h = sigf(eg) * tanhf_fast(c);
            s_c[t][r] = c;
            s_h[t][r] = h;
            if (i + 1 < NL)            // entry_h for layer i+1
                outq[(((size_t)(b0 + t) * RC + r)
                      + (size_t)(i + 1) * LSTR) * 129 + QL] = h;
        }
        GBAR(g);                       // group-local: s_h rows updated
    }

    // ---- trailing fc1 for layer 23's skip-h ----
    {
        const ulonglong2* f1p = wf1 + (size_t)(NL - 1) * (16 * 256);
        #pragma unroll 4
        for (int rc = 0; rc < RC; rc += 4) {
            ulonglong2 fA = __ldg(&f1p[(rc >> 2) << 8]);
            {
                ulonglong2 H = *(const ulonglong2*)&s_h[t0][rc];
                fma2(y0, H.x, fA.x);
                fma2(y0, H.y, fA.y);
            }
            {
                ulonglong2 H = *(const ulonglong2*)&s_h[t0 + 1][rc];
                fma2(y1, H.x, fA.x);
                fma2(y1, H.y, fA.y);
            }
        }
    }

    // ---- fc2: h_hat[b] = relu(y) @ fc2_w^T + fc2_b ----
    {
        float fw = fc2_w[j];
        s_co[t0][j]     = fmaxf(hadd2(y0), 0.0f) * fw;
        s_co[t0 + 1][j] = fmaxf(hadd2(y1), 0.0f) * fw;
    }
    __syncthreads();

    int w = tid >> 5, lane = tid & 31;
    if (w < TB) {                        // warps 0..3 reduce the TB rows
        float s = 0.0f;
        #pragma unroll
        for (int k = 0; k < 8; k++) s += s_co[w][lane + k * 32];
        #pragma unroll
        for (int o = 16; o > 0; o >>= 1) s += __shfl_xor_sync(0xffffffffu, s, o);
        if (lane == 0) out[b0 + w] = s + fc2_b[0];
    }
}

extern "C" void kernel_launch(void* const* d_in, const int* in_sizes, int n_in,
                              void* d_out, int out_size)
{
    const float* x        = (const float*)d_in[0];
    const float* features = (const float*)d_in[1];
    const float* queues   = (const float*)d_in[2];
    const float* fc_h_w   = (const float*)d_in[3];
    const float* fc_h_b   = (const float*)d_in[4];
    const float* fc_c_w   = (const float*)d_in[5];
    const float* fc_c_b   = (const float*)d_in[6];
    const float* conv_w   = (const float*)d_in[7];
    const float* conv_b   = (const float*)d_in[8];
    const float* fc1_w    = (const float*)d_in[9];
    const float* fc1_b    = (const float*)d_in[10];
    const float* fc2_w    = (const float*)d_in[11];
    const float* fc2_b    = (const float*)d_in[12];
    float* out = (float*)d_out;

    // Serial, single stream. COPY MUST PRECEDE COMPUTE: the copy writes junk
    // into the entry slots, which the compute kernel then overwrites.
    queue_copy_kernel<<<NCOPY, NTHREADS>>>(queues, out);

    transpose_weights_kernel<<<(NCONVP + NTHREADS - 1) / NTHREADS, NTHREADS>>>(
        conv_w, fc1_w);

    wave_compute_kernel<<<NCOMP, CTHREADS>>>(
        x, features, queues, fc_h_w, fc_h_b, fc_c_w, fc_c_b,
        conv_b, fc1_b, fc2_w, fc2_b, out);
}

// round 17
// speedup vs baseline: 1.0702x; 1.0702x over previous
#include <cuda_runtime.h>

#define BATCH 1024
#define RC 64
#define NL 24
#define QL 128
#define TB 4                     // batch rows per compute block
#define NCOMP (BATCH / TB)       // 256 compute blocks
#define CTHREADS 512             // 2 independent groups of 256
#define NTHREADS 256
#define NQ ((size_t)NL * BATCH * RC * QL)   // 201326592 queue elements
#define NROWS (NQ / 128)                    // 1572864 rows of 128 floats
#define LSTR ((size_t)BATCH * RC)           // row index stride per layer
#define NCONVP (NL * 32 * 256)              // packed conv float4 count
#define NFC1P  (NL * 16 * 256)              // packed fc1 float4 count

// ---- copy kernel geometry: 4-row groups are contiguous+aligned in dst ----
#define BG 8                                // 4-row groups per copy block
#define CP_ROWS (4 * BG)                    // 32 rows per block
#define CP_SRC_F4 (CP_ROWS * 128 / 4)       // 1024 src float4 per block
#define CP_DST_F  (CP_ROWS * 129)           // 4128 dst floats per block
#define CP_DST_F4 (CP_DST_F / 4)            // 1032 dst float4 per block
#define NCOPY ((int)(NROWS / CP_ROWS))      // 49152 copy blocks

typedef unsigned long long u64;

// Packed transposed weights, lane-coalesced for thread==j mapping.
// g_convP[(i*32+p)*256+j] = (w0[2p], w0[2p+1], w1[2p], w1[2p+1])
//   -> as ulonglong2: .x = f32x2 pair of w0, .y = f32x2 pair of w1
// g_fc1P [(i*16+q)*256+j] = fc1[rc=4q..4q+3] (two natural f32x2 pairs)
__device__ float4 g_convP[NCONVP];
__device__ float4 g_fc1P[NFC1P];

// Fast MUFU-based activations (ex2.approx + rcp.approx; ~1e-6 rel err).
__device__ __forceinline__ float sigf(float x) {
    return __fdividef(1.0f, 1.0f + __expf(-x));
}
__device__ __forceinline__ float tanhf_fast(float x) {
    return 1.0f - __fdividef(2.0f, __expf(2.0f * x) + 1.0f);
}

__device__ __forceinline__ void fma2(u64& d, u64 a, u64 b) {
    asm("fma.rn.f32x2 %0, %1, %2, %3;" : "=l"(d) : "l"(a), "l"(b), "l"(d));
}
__device__ __forceinline__ u64 pk(float lo, float hi) {
    u64 r; asm("mov.b64 %0, {%1, %2};" : "=l"(r) : "f"(lo), "f"(hi)); return r;
}
__device__ __forceinline__ float hadd2(u64 v) {
    float lo, hi;
    asm("mov.b64 {%0, %1}, %2;" : "=f"(lo), "=f"(hi) : "l"(v));
    return lo + hi;
}

#define GBAR(g) asm volatile("bar.sync %0, %1;" :: "r"((g) + 1), "r"(256) : "memory")

// ---------------------------------------------------------------------------
// WEIGHT TRANSPOSE (packed float4, rc-pairwise reorder for f32x2)
// ---------------------------------------------------------------------------
__global__ void __launch_bounds__(NTHREADS)
transpose_weights_kernel(const float* __restrict__ conv_w,
                         const float* __restrict__ fc1_w)
{
    int idx = blockIdx.x * NTHREADS + threadIdx.x;   // ((i*32+p)*256+j)
    if (idx < NCONVP) {
        int j  = idx & 255;
        int pi = idx >> 8;           // i*32 + p
        int p  = pi & 31;
        int i  = pi >> 5;
        float4 v =
            __ldg((const float4*)(conv_w + (((size_t)i * 256 + j) << 7)) + p);
        // src float4 #p = (w0[2p], w1[2p], w0[2p+1], w1[2p+1])
        g_convP[idx] = make_float4(v.x, v.z, v.y, v.w);
    }
    if (idx < NFC1P) {
        int j  = idx & 255;
        int qi = idx >> 8;           // i*16 + q
        g_fc1P[idx] =
            __ldg((const float4*)(fc1_w + (size_t)j * (NL * RC)) + qi);
    }
}

// ---------------------------------------------------------------------------
// COPY KERNEL v2: fully-aligned stream copy with smem hole insertion.
// (Proven: 228us standalone, 86.5% DRAM.)
// ---------------------------------------------------------------------------
__global__ void __launch_bounds__(NTHREADS)
queue_copy_kernel(const float* __restrict__ queues, float* __restrict__ out)
{
    __shared__ __align__(16) float st[CP_DST_F];
    const int tid = threadIdx.x;
    const size_t blk = blockIdx.x;

    const float4* __restrict__ s4 = (const float4*)queues + blk * CP_SRC_F4;
    #pragma unroll
    for (int k = 0; k < CP_SRC_F4 / NTHREADS; k++) {      // 4 iterations
        int e4 = k * NTHREADS + tid;
        float4 v = __ldcs(&s4[e4]);
        int e  = e4 * 4;
        int ep = e + (e >> 7);
        st[ep]     = v.x;
        st[ep + 1] = v.y;
        st[ep + 2] = v.z;
        st[ep + 3] = v.w;
    }
    if (tid < CP_ROWS) st[tid * 129 + 128] = 0.0f;        // junk in holes
    __syncthreads();

    float4* __restrict__ d4 = (float4*)(out + BATCH) + blk * CP_DST_F4;
    #pragma unroll
    for (int k = 0; k < (CP_DST_F4 + NTHREADS - 1) / NTHREADS; k++) {
        int e4 = k * NTHREADS + tid;
        if (e4 < CP_DST_F4)
            __stcs(&d4[e4], *(const float4*)&st[e4 * 4]);
    }
}

// ---------------------------------------------------------------------------
// COMPUTE KERNEL: exact R15 structure (479.2us proven) with MUFU activations
// as the single change. 512 threads, TB=4 rows, two independent 256-thread
// groups; per-layer group-local barriers; fc1 of layer i-1 fused into layer
// i's conv loop; packed f32x2 FMAs.
// ---------------------------------------------------------------------------
__global__ void __launch_bounds__(CTHREADS, 2)
wave_compute_kernel(const float* __restrict__ x,
                    const float* __restrict__ features,
                    const float* __restrict__ queues,
                    const float* __restrict__ fc_h_w,
                    const float* __restrict__ fc_h_b,
                    const float* __restrict__ fc_c_w,
                    const float* __restrict__ fc_c_b,
                    const float* __restrict__ conv_b,
                    const float* __restrict__ fc1_b,
                    const float* __restrict__ fc2_w,
                    const float* __restrict__ fc2_b,
                    float* __restrict__ out)
{
    __shared__ __align__(16) float s_h[TB][RC];
    __shared__ __align__(16) float s_c[TB][RC];
    __shared__ __align__(16) float s_pv[NL][TB][RC];   // 24 KB prefetched slices
    __shared__ float s_co[TB][4 * RC];

    const int tid = threadIdx.x;
    const int b0  = blockIdx.x * TB;
    const int g   = tid >> 8;          // group 0/1: owns rows t0, t0+1
    const int lid = tid & 255;         // id within group
    const int j   = lid;               // output channel
    const int t0  = g * 2;

    // ---- prefetch ALL 24 layers' dilated queue values into shared ----
    for (int idx = tid; idx < NL * TB * RC; idx += CTHREADS) {
        int i = idx >> 8;              // / (TB*RC)
        int t = (idx >> 6) & 3;
        int r = idx & 63;
        s_pv[i][t][r] = __ldg(queues
            + (((size_t)(b0 + t) * RC + r) + (size_t)i * LSTR) * QL
            + QL - (1 << (i & 7)));
    }

    // ---- initial h, c (each group inits its own 2 rows; 128 threads) ----
    float* __restrict__ outq = out + BATCH;
    if (lid < 128) {
        int t = t0 + (lid >> 6), r = lid & 63;
        int b = b0 + t;
        const float* wh = fc_h_w + r * 33;
        const float* wc = fc_c_w + r * 33;
        float ah = fc_h_b[r], ac = fc_c_b[r];
        float xv = x[b];
        ah += xv * wh[0];
        ac += xv * wc[0];
        const float* fb = features + b * 32;
        #pragma unroll
        for (int k = 0; k < 32; k++) {
            float f = fb[k];
            ah += f * wh[1 + k];
            ac += f * wc[1 + k];
        }
        float h0 = tanhf_fast(ah);
        s_h[t][r] = h0;
        s_c[t][r] = tanhf_fast(ac);
        outq[((size_t)b * RC + r) * 129 + QL] = h0;    // entry for layer 0
    }

    u64 y0 = pk(fc1_b[j], 0.0f), y1 = y0;
    __syncthreads();                   // s_pv + init visible to all

    const ulonglong2* __restrict__ wcv = (const ulonglong2*)g_convP + j;
    const ulonglong2* __restrict__ wf1 = (const ulonglong2*)g_fc1P  + j;

    for (int i = 0; i < NL; i++) {
        // ---- conv layer i (+ fused fc1 of layer i-1, same s_h reads) ----
        u64 acc0 = pk(__ldg(conv_b + i * 256 + j), 0.0f);
        u64 acc1 = acc0;
        const ulonglong2* wci = wcv + (size_t)i * (32 * 256);
        const ulonglong2* f1p = wf1 + (size_t)(i - 1) * (16 * 256);
        const bool addf = (i > 0);
        #pragma unroll 4
        for (int rc = 0; rc < RC; rc += 4) {
            // wA: rc,rc+1  (.x = w0 pair, .y = w1 pair); wB: rc+2,rc+3
            ulonglong2 wA = __ldg(&wci[((rc >> 1)    ) << 8]);
            ulonglong2 wB = __ldg(&wci[((rc >> 1) + 1) << 8]);
            ulonglong2 fA = make_ulonglong2(0ull, 0ull);
            if (addf) fA = __ldg(&f1p[(rc >> 2) << 8]);
            {
                ulonglong2 P = *(const ulonglong2*)&s_pv[i][t0][rc];
                ulonglong2 H = *(const ulonglong2*)&s_h[t0][rc];
                fma2(acc0, P.x, wA.x);
                fma2(acc0, H.x, wA.y);
                fma2(acc0, P.y, wB.x);
                fma2(acc0, H.y, wB.y);
                fma2(y0,   H.x, fA.x);
                fma2(y0,   H.y, fA.y);
            }
            {
                ulonglong2 P = *(const ulonglong2*)&s_pv[i][t0 + 1][rc];
                ulonglong2 H = *(const ulonglong2*)&s_h[t0 + 1][rc];
                fma2(acc1, P.x, wA.x);
                fma2(acc1, H.x, wA.y);
                fma2(acc1, P.y, wB.x);
                fma2(acc1, H.y, wB.y);
                fma2(y1,   H.x, fA.x);
                fma2(y1,   H.y, fA.y);
            }
        }
        s_co[t0][j]     = hadd2(acc0);
        s_co[t0 + 1][j] = hadd2(acc1);
        GBAR(g);                       // group-local: s_co rows ready

        // ---- gate update: lower 128 threads of this group, own rows ----
        if (lid < 128) {
            int t = t0 + (lid >> 6), r = lid & 63;
            float ig = s_co[t][r];
            float cf = s_co[t][RC + r];
            float cg = s_co[t][2 * RC + r];
            float eg = s_co[t][3 * RC + r];
            float c = sigf(ig) * s_c[t][r] + tanhf_fast(cf) * sigf(cg);
            float h = sigf(eg) * tanhf_fast(c);
            s_c[t][r] = c;
            s_h[t][r] = h;
            if (i + 1 < NL)            // entry_h for layer i+1
                outq[(((size_t)(b0 + t) * RC + r)
                      + (size_t)(i + 1) * LSTR) * 129 + QL] = h;
        }
        GBAR(g);                       // group-local: s_h rows updated
    }

    // ---- trailing fc1 for layer 23's skip-h ----
    {
        const ulonglong2* f1p = wf1 + (size_t)(NL - 1) * (16 * 256);
        #pragma unroll 4
        for (int rc = 0; rc < RC; rc += 4) {
            ulonglong2 fA = __ldg(&f1p[(rc >> 2) << 8]);
            {
                ulonglong2 H = *(const ulonglong2*)&s_h[t0][rc];
                fma2(y0, H.x, fA.x);
                fma2(y0, H.y, fA.y);
            }
            {
                ulonglong2 H = *(const ulonglong2*)&s_h[t0 + 1][rc];
                fma2(y1, H.x, fA.x);
                fma2(y1, H.y, fA.y);
            }
        }
    }

    // ---- fc2: h_hat[b] = relu(y) @ fc2_w^T + fc2_b ----
    {
        float fw = fc2_w[j];
        s_co[t0][j]     = fmaxf(hadd2(y0), 0.0f) * fw;
        s_co[t0 + 1][j] = fmaxf(hadd2(y1), 0.0f) * fw;
    }
    __syncthreads();

    int w = tid >> 5, lane = tid & 31;
    if (w < TB) {                        // warps 0..3 reduce the TB rows
        float s = 0.0f;
        #pragma unroll
        for (int k = 0; k < 8; k++) s += s_co[w][lane + k * 32];
        #pragma unroll
        for (int o = 16; o > 0; o >>= 1) s += __shfl_xor_sync(0xffffffffu, s, o);
        if (lane == 0) out[b0 + w] = s + fc2_b[0];
    }
}

extern "C" void kernel_launch(void* const* d_in, const int* in_sizes, int n_in,
                              void* d_out, int out_size)
{
    const float* x        = (const float*)d_in[0];
    const float* features = (const float*)d_in[1];
    const float* queues   = (const float*)d_in[2];
    const float* fc_h_w   = (const float*)d_in[3];
    const float* fc_h_b   = (const float*)d_in[4];
    const float* fc_c_w   = (const float*)d_in[5];
    const float* fc_c_b   = (const float*)d_in[6];
    const float* conv_w   = (const float*)d_in[7];
    const float* conv_b   = (const float*)d_in[8];
    const float* fc1_w    = (const float*)d_in[9];
    const float* fc1_b    = (const float*)d_in[10];
    const float* fc2_w    = (const float*)d_in[11];
    const float* fc2_b    = (const float*)d_in[12];
    float* out = (float*)d_out;

    // Serial, single stream. COPY MUST PRECEDE COMPUTE: the copy writes junk
    // into the entry slots, which the compute kernel then overwrites.
    queue_copy_kernel<<<NCOPY, NTHREADS>>>(queues, out);

    transpose_weights_kernel<<<(NCONVP + NTHREADS - 1) / NTHREADS, NTHREADS>>>(
        conv_w, fc1_w);

    wave_compute_kernel<<<NCOMP, CTHREADS>>>(
        x, features, queues, fc_h_w, fc_h_b, fc_c_w, fc_c_b,
        conv_b, fc1_b, fc2_w, fc2_b, out);
}